// round 2
// baseline (speedup 1.0000x reference)
#include <cuda_runtime.h>

// ---------------------------------------------------------------------------
// LaplacianPyramid: out[b,h,w] = sum over 4 layers of bilinear(layer, uv[b,h,w])
// uv is uniform random -> gathers are fully scattered. Strategy: pre-pack each
// layer into a zero-padded (S+1)x(S+1) float4 array holding the full 2x2
// bilinear footprint, so each sample is ONE aligned LDG.128 instead of 4
// scalar LDGs (4x fewer L1tex wavefronts).
// ---------------------------------------------------------------------------

// Packed 2x2 footprint tables (zero-padded borders). ~89 MB total, static
// __device__ globals (no allocation anywhere, per harness rules).
__device__ float4 g_P1[2049 * 2049];
__device__ float4 g_P2[1025 * 1025];
__device__ float4 g_P3[513 * 513];
__device__ float4 g_P4[257 * 257];

template <int S>
__device__ __forceinline__ float4* packed_buf() {
    if constexpr (S == 2048) return g_P1;
    else if constexpr (S == 1024) return g_P2;
    else if constexpr (S == 512) return g_P3;
    else return g_P4;
}

// Build P[yi][xi] = (img[y0][x0], img[y0][x0+1], img[y1][x0], img[y1][x1])
// with y0 = yi-1, x0 = xi-1 and zeros for out-of-range taps
// (== padding_mode='zeros' semantics baked into the table).
template <int S>
__global__ void __launch_bounds__(256) pack_kernel(const float* __restrict__ src) {
    int xi = blockIdx.x * blockDim.x + threadIdx.x;  // [0, S]
    int yi = blockIdx.y;                             // [0, S]
    if (xi > S) return;

    int x0 = xi - 1;
    int y0 = yi - 1;
    bool xl = (x0 >= 0);
    bool xr = (x0 < S - 1);  // x0+1 in range
    bool yt = (y0 >= 0);
    bool yb = (y0 < S - 1);  // y0+1 in range

    float v00 = 0.f, v01 = 0.f, v10 = 0.f, v11 = 0.f;
    if (yt) {
        const float* r = src + (long long)y0 * S;
        if (xl) v00 = r[x0];
        if (xr) v01 = r[x0 + 1];
    }
    if (yb) {
        const float* r = src + (long long)(y0 + 1) * S;
        if (xl) v10 = r[x0];
        if (xr) v11 = r[x0 + 1];
    }
    packed_buf<S>()[yi * (S + 1) + xi] = make_float4(v00, v01, v10, v11);
}

// One bilinear sample from a packed table. Reference unnormalization
// collapses to x = u*S - 0.5 (grid = 2u-1; x = (grid+1)*S/2 - 0.5).
template <int S>
__device__ __forceinline__ float sample1(float u, float v) {
    float x = fmaf(u, (float)S, -0.5f);
    float y = fmaf(v, (float)S, -0.5f);
    float xf = floorf(x);
    float yf = floorf(y);
    float wx = x - xf;
    float wy = y - yf;
    int xi = (int)xf + 1;
    int yi = (int)yf + 1;
    // uv in [0,1) keeps these in [0,S] already; clamp for safety (no-op cost).
    xi = max(0, min(S, xi));
    yi = max(0, min(S, yi));
    float4 t = __ldg(packed_buf<S>() + (yi * (S + 1) + xi));
    float top = fmaf(wx, t.y - t.x, t.x);
    float bot = fmaf(wx, t.w - t.z, t.z);
    return fmaf(wy, bot - top, top);
}

__global__ void __launch_bounds__(256) gather_kernel(
    const float2* __restrict__ uv, float* __restrict__ out, int n) {
    int i = blockIdx.x * blockDim.x + threadIdx.x;
    if (i >= n) return;
    float2 g = __ldg(uv + i);
    // Four independent LDG.128s -> good MLP; compiler hoists the loads.
    float a0 = sample1<2048>(g.x, g.y);
    float a1 = sample1<1024>(g.x, g.y);
    float a2 = sample1<512>(g.x, g.y);
    float a3 = sample1<256>(g.x, g.y);
    out[i] = (a0 + a1) + (a2 + a3);
}

extern "C" void kernel_launch(void* const* d_in, const int* in_sizes, int n_in,
                              void* d_out, int out_size) {
    const float* uv = (const float*)d_in[0];
    const float* l1 = (const float*)d_in[1];  // 2048 x 2048
    const float* l2 = (const float*)d_in[2];  // 1024 x 1024
    const float* l3 = (const float*)d_in[3];  // 512  x 512
    const float* l4 = (const float*)d_in[4];  // 256  x 256

    // Rebuild packed tables every call (determinism / no caching).
    pack_kernel<2048><<<dim3((2049 + 255) / 256, 2049), 256>>>(l1);
    pack_kernel<1024><<<dim3((1025 + 255) / 256, 1025), 256>>>(l2);
    pack_kernel<512><<<dim3((513 + 255) / 256, 513), 256>>>(l3);
    pack_kernel<256><<<dim3((257 + 255) / 256, 257), 256>>>(l4);

    int n = out_size;  // 8 * 1024 * 1024
    gather_kernel<<<(n + 255) / 256, 256>>>((const float2*)uv, (float*)d_out, n);
}